// round 10
// baseline (speedup 1.0000x reference)
#include <cuda_runtime.h>
#include <cuda_fp16.h>
#include <mma.h>
#include <cstdint>

using namespace nvcuda;

// ---------------- problem constants ----------------
#define BATCH   8
#define NT      8192
#define NS      2048
#define NTOT    (BATCH * NT)      // 65536 target rows
#define C_TGT   128
#define C_SRC   256
#define C_IN    384
#define C_HID   256
#define C_OUT   128

// ---------------- device scratch (no allocs allowed) ----------------
__device__ __align__(128) int    g_knn_idx[NTOT * 3];
__device__ __align__(128) float  g_knn_w  [NTOT * 3];
__device__ __align__(128) __half g_interp_h[NTOT * C_SRC];   // 32 MB
__device__ __align__(128) __half g_hidden_h[NTOT * C_HID];   // 32 MB
__device__ __align__(128) __half g_xt_h   [NTOT * C_TGT];    // 16 MB
__device__ __align__(128) __half g_W1_h   [C_IN * C_HID];
__device__ __align__(128) __half g_Wcat_h [(C_HID + C_IN) * C_OUT];  // [W2;Ws] 640x128
__device__ __align__(128) float  g_bcat   [C_OUT];                   // b2+bs

// ============================================================
// cp.async helpers
// ============================================================
__device__ __forceinline__ void cp16h(__half* dst_smem, const __half* src_gmem) {
    uint32_t d = (uint32_t)__cvta_generic_to_shared(dst_smem);
    asm volatile("cp.async.cg.shared.global [%0], [%1], 16;\n" :: "r"(d), "l"(src_gmem));
}
__device__ __forceinline__ void cp_commit() {
    asm volatile("cp.async.commit_group;\n");
}
template<int N>
__device__ __forceinline__ void cp_wait() {
    asm volatile("cp.async.wait_group %0;\n" :: "n"(N));
}

// ============================================================
// Convert kernels (run once per launch; tiny)
// ============================================================
__global__ __launch_bounds__(256)
void cvt_xt_kernel(const float* __restrict__ xt)
{
    const int i4 = blockIdx.x * 256 + threadIdx.x;     // float4 index
    float4 v = ((const float4*)xt)[i4];
    __half2* p = (__half2*)&g_xt_h[i4 * 4];
    p[0] = __floats2half2_rn(v.x, v.y);
    p[1] = __floats2half2_rn(v.z, v.w);
}

__global__ __launch_bounds__(256)
void cvt_weights_kernel(const float* __restrict__ W1,
                        const float* __restrict__ W2,
                        const float* __restrict__ Ws,
                        const float* __restrict__ b2,
                        const float* __restrict__ bs)
{
    const int i = blockIdx.x * 256 + threadIdx.x;
    if (i < C_IN * C_HID)            g_W1_h[i] = __float2half_rn(W1[i]);
    if (i < C_HID * C_OUT)           g_Wcat_h[i] = __float2half_rn(W2[i]);
    if (i < C_IN * C_OUT)            g_Wcat_h[C_HID * C_OUT + i] = __float2half_rn(Ws[i]);
    if (i < C_OUT)                   g_bcat[i] = b2[i] + bs[i];
}

// ============================================================
// Kernel 1: brute-force 3-NN per target within its batch.
// ============================================================
__global__ __launch_bounds__(256)
void knn_kernel(const float* __restrict__ pos_t, const float* __restrict__ pos_s)
{
    __shared__ float4 sp[NS];             // 32 KB
    const int b    = blockIdx.x >> 5;
    const int tile = blockIdx.x & 31;

    const float* ps = pos_s + (size_t)b * NS * 3;
    for (int s = threadIdx.x; s < NS; s += 256) {
        sp[s] = make_float4(ps[3*s], ps[3*s+1], ps[3*s+2], 0.f);
    }
    __syncthreads();

    const int t = (b * 32 + tile) * 256 + threadIdx.x;
    const float tx = pos_t[3*t], ty = pos_t[3*t+1], tz = pos_t[3*t+2];

    float d0 = 1e30f, d1 = 1e30f, d2 = 1e30f;
    int   i0 = 0,     i1 = 0,     i2 = 0;

    #pragma unroll 4
    for (int s = 0; s < NS; ++s) {
        float4 p = sp[s];
        float dx = tx - p.x, dy = ty - p.y, dz = tz - p.z;
        float d  = fmaf(dz, dz, fmaf(dy, dy, dx * dx));
        if (d < d2) {
            if (d < d1) {
                d2 = d1; i2 = i1;
                if (d < d0) { d1 = d0; i1 = i0; d0 = d; i0 = s; }
                else        { d1 = d;  i1 = s; }
            } else { d2 = d; i2 = s; }
        }
    }

    const float w0 = 1.f / fmaxf(d0, 1e-16f);
    const float w1 = 1.f / fmaxf(d1, 1e-16f);
    const float w2 = 1.f / fmaxf(d2, 1e-16f);
    const float inv = 1.f / (w0 + w1 + w2);

    g_knn_w[3*t+0] = w0 * inv;
    g_knn_w[3*t+1] = w1 * inv;
    g_knn_w[3*t+2] = w2 * inv;
    g_knn_idx[3*t+0] = b * NS + i0;
    g_knn_idx[3*t+1] = b * NS + i1;
    g_knn_idx[3*t+2] = b * NS + i2;
}

// ============================================================
// Kernel 2: interpolation gather -> half output.
// ============================================================
__global__ __launch_bounds__(256)
void interp_kernel(const float* __restrict__ xs)
{
    const int row  = blockIdx.x * 8 + (threadIdx.x >> 5);
    const int lane = threadIdx.x & 31;

    const int   i0 = g_knn_idx[3*row+0];
    const int   i1 = g_knn_idx[3*row+1];
    const int   i2 = g_knn_idx[3*row+2];
    const float w0 = g_knn_w[3*row+0];
    const float w1 = g_knn_w[3*row+1];
    const float w2 = g_knn_w[3*row+2];

    const float4* s0 = (const float4*)(xs + (size_t)i0 * C_SRC);
    const float4* s1 = (const float4*)(xs + (size_t)i1 * C_SRC);
    const float4* s2 = (const float4*)(xs + (size_t)i2 * C_SRC);
    __half2* dst = (__half2*)&g_interp_h[(size_t)row * C_SRC];

    #pragma unroll
    for (int h = 0; h < 2; ++h) {
        const int c = lane + h * 32;          // float4 index, 64/row
        float4 a = s0[c], b = s1[c], d = s2[c];
        float rx = w0*a.x + w1*b.x + w2*d.x;
        float ry = w0*a.y + w1*b.y + w2*d.y;
        float rz = w0*a.z + w1*b.z + w2*d.z;
        float rw = w0*a.w + w1*b.w + w2*d.w;
        dst[c*2+0] = __floats2half2_rn(rx, ry);
        dst[c*2+1] = __floats2half2_rn(rz, rw);
    }
}

// ============================================================
// half GEMM: 128x128 tile, 8 warps (4x2), KC=32, cp.async 3-stage.
// ============================================================
#define KC      32
#define PIPE    3
#define SA_LD   40                      // halves/row (32 + 8 pad)
#define SB_LD   136                     // halves/row (128 + 8 pad)
#define SA_HSZ  (128 * SA_LD)           // 5120
#define SB_HSZ  (KC * SB_LD)            // 4352
#define STG_H   (SA_HSZ + SB_HSZ)       // 9472 halves / stage
#define SMEM_BYTES (PIPE * STG_H * 2)   // 56832 B

using FragA = wmma::fragment<wmma::matrix_a, 16, 16, 16, __half, wmma::row_major>;
using FragB = wmma::fragment<wmma::matrix_b, 16, 16, 16, __half, wmma::row_major>;
using FragC = wmma::fragment<wmma::accumulator, 16, 16, 16, float>;

// stage A(128xKC) + B(KCx128) half tiles via cp.async
__device__ __forceinline__ void stage_tiles(
    __half* sA, __half* sB, int tid, int m0,
    const __half* __restrict__ abase, int astride, int aoff,
    const __half* __restrict__ bbase, int bstride, int boff, int n0)
{
    #pragma unroll
    for (int tI = 0; tI < 2; ++tI) {
        const int i = tid + tI * 256;          // 512 chunks of 8 halves
        const int r  = i >> 2;                 // 0..127
        const int c8 = (i & 3) << 3;           // 0,8,16,24
        cp16h(&sA[r * SA_LD + c8], abase + (size_t)(m0 + r) * astride + aoff + c8);
    }
    #pragma unroll
    for (int tI = 0; tI < 2; ++tI) {
        const int i = tid + tI * 256;
        const int r  = i >> 4;                 // 0..31
        const int c8 = (i & 15) << 3;          // 0..120
        cp16h(&sB[r * SB_LD + c8], bbase + (size_t)(boff + r) * bstride + n0 + c8);
    }
}

// consume one KC=32 chunk: 2 x (6 frag loads + 8 mma) per warp
__device__ __forceinline__ void compute_chunk(
    const __half* sA, const __half* sB, int warp_m, int warp_n, FragC fc[2][4])
{
    #pragma unroll
    for (int k16 = 0; k16 < KC; k16 += 16) {
        FragA fa[2];
        FragB fb[4];
        #pragma unroll
        for (int i = 0; i < 2; ++i)
            wmma::load_matrix_sync(fa[i], &sA[(warp_m*32 + i*16) * SA_LD + k16], SA_LD);
        #pragma unroll
        for (int j = 0; j < 4; ++j)
            wmma::load_matrix_sync(fb[j], &sB[k16 * SB_LD + warp_n*64 + j*16], SB_LD);
        #pragma unroll
        for (int i = 0; i < 2; ++i)
            #pragma unroll
            for (int j = 0; j < 4; ++j)
                wmma::mma_sync(fc[i][j], fa[i], fb[j], fc[i][j]);
    }
}

// ------------------------------------------------------------
// GEMM1: hidden = relu([xt | interp] @ W1 + b1)  K=384, N=256 -> half
// ------------------------------------------------------------
__global__ __launch_bounds__(256, 2)
void gemm1_kernel(const float* __restrict__ b1)
{
    extern __shared__ __align__(16) __half sh[];
    const int m0 = blockIdx.x * 128;
    const int n0 = blockIdx.y * 128;
    const int tid = threadIdx.x;
    const int w   = tid >> 5;
    const int warp_m = w & 3;
    const int warp_n = w >> 2;
    const int lane = tid & 31;

    FragC fc[2][4];
    #pragma unroll
    for (int i = 0; i < 2; ++i)
        #pragma unroll
        for (int j = 0; j < 4; ++j)
            wmma::fill_fragment(fc[i][j], 0.f);

    auto stage_it = [&](int it) {
        const int kc = it * KC;
        const __half* ab; int as, ao;
        if (kc < C_TGT) { ab = g_xt_h;     as = C_TGT; ao = kc;         }
        else            { ab = g_interp_h; as = C_SRC; ao = kc - C_TGT; }
        __half* st = sh + (it % PIPE) * STG_H;
        stage_tiles(st, st + SA_HSZ, tid, m0, ab, as, ao, g_W1_h, C_HID, kc, n0);
        cp_commit();
    };

    const int NITER = C_IN / KC;   // 12
    stage_it(0);
    stage_it(1);

    for (int it = 0; it < NITER; ++it) {
        cp_wait<1>();
        __syncthreads();
        if (it + 2 < NITER) stage_it(it + 2);
        const __half* st = sh + (it % PIPE) * STG_H;
        compute_chunk(st, st + SA_HSZ, warp_m, warp_n, fc);
    }
    __syncthreads();

    // epilogue: bias + relu -> half hidden
    float* wb = (float*)sh + w * 1024;
    const int gm_base = m0 + warp_m * 32;
    const int gn_base = n0 + warp_n * 64;
    #pragma unroll
    for (int i = 0; i < 2; ++i) {
        #pragma unroll
        for (int j = 0; j < 4; ++j)
            wmma::store_matrix_sync(wb + j*16, fc[i][j], 64, wmma::mem_row_major);
        __syncwarp();
        #pragma unroll
        for (int e = lane; e < 256; e += 32) {
            const int rr = e >> 4;
            const int cc = (e & 15) << 2;
            float4 v = *(float4*)(wb + rr*64 + cc);
            const int gn = gn_base + cc;
            v.x = fmaxf(v.x + b1[gn+0], 0.f);
            v.y = fmaxf(v.y + b1[gn+1], 0.f);
            v.z = fmaxf(v.z + b1[gn+2], 0.f);
            v.w = fmaxf(v.w + b1[gn+3], 0.f);
            __half2 h01 = __floats2half2_rn(v.x, v.y);
            __half2 h23 = __floats2half2_rn(v.z, v.w);
            __half2* p = (__half2*)&g_hidden_h[(size_t)(gm_base + i*16 + rr) * C_HID + gn];
            p[0] = h01; p[1] = h23;
        }
        __syncwarp();
    }
}

// ------------------------------------------------------------
// GEMM2: out = relu([hidden | xt | interp] @ Wcat + bcat)  K=640, N=128
// ------------------------------------------------------------
__global__ __launch_bounds__(256, 2)
void gemm2_kernel(float* __restrict__ out)
{
    extern __shared__ __align__(16) __half sh[];
    const int m0 = blockIdx.x * 128;
    const int tid = threadIdx.x;
    const int w   = tid >> 5;
    const int warp_m = w & 3;
    const int warp_n = w >> 2;
    const int lane = tid & 31;

    FragC fc[2][4];
    #pragma unroll
    for (int i = 0; i < 2; ++i)
        #pragma unroll
        for (int j = 0; j < 4; ++j)
            wmma::fill_fragment(fc[i][j], 0.f);

    auto stage_it = [&](int it) {
        const int kc = it * KC;
        const __half* ab; int as, ao;
        if      (kc < 256) { ab = g_hidden_h; as = C_HID; ao = kc;       }
        else if (kc < 384) { ab = g_xt_h;     as = C_TGT; ao = kc - 256; }
        else               { ab = g_interp_h; as = C_SRC; ao = kc - 384; }
        __half* st = sh + (it % PIPE) * STG_H;
        stage_tiles(st, st + SA_HSZ, tid, m0, ab, as, ao, g_Wcat_h, C_OUT, kc, 0);
        cp_commit();
    };

    const int NITER = (C_HID + C_IN) / KC;   // 20
    stage_it(0);
    stage_it(1);

    for (int it = 0; it < NITER; ++it) {
        cp_wait<1>();
        __syncthreads();
        if (it + 2 < NITER) stage_it(it + 2);
        const __half* st = sh + (it % PIPE) * STG_H;
        compute_chunk(st, st + SA_HSZ, warp_m, warp_n, fc);
    }
    __syncthreads();

    // epilogue: bcat + relu -> fp32 out
    float* wb = (float*)sh + w * 1024;
    const int gm_base = m0 + warp_m * 32;
    const int gn_base = warp_n * 64;
    #pragma unroll
    for (int i = 0; i < 2; ++i) {
        #pragma unroll
        for (int j = 0; j < 4; ++j)
            wmma::store_matrix_sync(wb + j*16, fc[i][j], 64, wmma::mem_row_major);
        __syncwarp();
        #pragma unroll
        for (int e = lane; e < 256; e += 32) {
            const int rr = e >> 4;
            const int cc = (e & 15) << 2;
            float4 v = *(float4*)(wb + rr*64 + cc);
            const int gn = gn_base + cc;
            v.x = fmaxf(v.x + g_bcat[gn+0], 0.f);
            v.y = fmaxf(v.y + g_bcat[gn+1], 0.f);
            v.z = fmaxf(v.z + g_bcat[gn+2], 0.f);
            v.w = fmaxf(v.w + g_bcat[gn+3], 0.f);
            *(float4*)(&out[(size_t)(gm_base + i*16 + rr) * C_OUT + gn]) = v;
        }
        __syncwarp();
    }
}

// ============================================================
// Launch.
// ============================================================
extern "C" void kernel_launch(void* const* d_in, const int* in_sizes, int n_in,
                              void* d_out, int out_size)
{
    const float* xt = (const float*)d_in[0];
    const float* pt = (const float*)d_in[1];
    const float* xs = (const float*)d_in[3];
    const float* ps = (const float*)d_in[4];
    const float* W1 = (const float*)d_in[6];
    const float* b1 = (const float*)d_in[7];
    const float* W2 = (const float*)d_in[8];
    const float* b2 = (const float*)d_in[9];
    const float* Ws = (const float*)d_in[10];
    const float* bs = (const float*)d_in[11];
    float* out = (float*)d_out;

    cudaFuncSetAttribute(gemm1_kernel, cudaFuncAttributeMaxDynamicSharedMemorySize, SMEM_BYTES);
    cudaFuncSetAttribute(gemm2_kernel, cudaFuncAttributeMaxDynamicSharedMemorySize, SMEM_BYTES);

    cvt_xt_kernel     <<<NTOT * C_TGT / 4 / 256, 256>>>(xt);
    cvt_weights_kernel<<<(C_IN * C_HID + 255) / 256, 256>>>(W1, W2, Ws, b2, bs);
    knn_kernel        <<<BATCH * (NT / 256), 256>>>(pt, ps);
    interp_kernel     <<<NTOT / 8, 256>>>(xs);
    gemm1_kernel      <<<dim3(NTOT / 128, C_HID / 128), 256, SMEM_BYTES>>>(b1);
    gemm2_kernel      <<<dim3(NTOT / 128, 1), 256, SMEM_BYTES>>>(out);
}

// round 11
// speedup vs baseline: 1.0428x; 1.0428x over previous
#include <cuda_runtime.h>
#include <cuda_fp16.h>
#include <mma.h>
#include <cstdint>

using namespace nvcuda;

// ---------------- problem constants ----------------
#define BATCH   8
#define NT      8192
#define NS      2048
#define NTOT    (BATCH * NT)      // 65536 target rows
#define C_TGT   128
#define C_SRC   256
#define C_IN    384
#define C_HID   256
#define C_OUT   128
#define KC      32

// ---------------- device scratch (no allocs allowed) ----------------
__device__ __align__(128) int    g_knn_idx[NTOT * 3];
__device__ __align__(128) float  g_knn_w  [NTOT * 3];
__device__ __align__(128) __half g_W1_h   [C_IN * C_HID];
__device__ __align__(128) __half g_Wcat_h [(C_HID + C_IN) * C_OUT];  // [W2;Ws] 640x128
__device__ __align__(128) float  g_bcat   [C_OUT];                   // b2+bs

// ============================================================
// cp.async helpers
// ============================================================
__device__ __forceinline__ void cp16h(__half* dst_smem, const __half* src_gmem) {
    uint32_t d = (uint32_t)__cvta_generic_to_shared(dst_smem);
    asm volatile("cp.async.cg.shared.global [%0], [%1], 16;\n" :: "r"(d), "l"(src_gmem));
}
__device__ __forceinline__ void cp_commit() {
    asm volatile("cp.async.commit_group;\n");
}
template<int N>
__device__ __forceinline__ void cp_wait() {
    asm volatile("cp.async.wait_group %0;\n" :: "n"(N));
}

// ============================================================
// Weight conversion (tiny, once per launch)
// ============================================================
__global__ __launch_bounds__(256)
void cvt_weights_kernel(const float* __restrict__ W1,
                        const float* __restrict__ W2,
                        const float* __restrict__ Ws,
                        const float* __restrict__ b2,
                        const float* __restrict__ bs)
{
    const int i = blockIdx.x * 256 + threadIdx.x;
    if (i < C_IN * C_HID)   g_W1_h[i] = __float2half_rn(W1[i]);
    if (i < C_HID * C_OUT)  g_Wcat_h[i] = __float2half_rn(W2[i]);
    if (i < C_IN * C_OUT)   g_Wcat_h[C_HID * C_OUT + i] = __float2half_rn(Ws[i]);
    if (i < C_OUT)          g_bcat[i] = b2[i] + bs[i];
}

// ============================================================
// Kernel 1: 3-NN, split-2 — two threads per target, merged via shfl.
// Block: 256 threads = 128 targets; 64 tiles per batch.
// ============================================================
__global__ __launch_bounds__(256)
void knn_kernel(const float* __restrict__ pos_t, const float* __restrict__ pos_s)
{
    __shared__ float4 sp[NS];             // 32 KB
    const int b    = blockIdx.x >> 6;
    const int tile = blockIdx.x & 63;

    const float* ps = pos_s + (size_t)b * NS * 3;
    for (int s = threadIdx.x; s < NS; s += 256)
        sp[s] = make_float4(ps[3*s], ps[3*s+1], ps[3*s+2], 0.f);
    __syncthreads();

    const int tl   = threadIdx.x >> 1;
    const int half = threadIdx.x & 1;
    const int t = (b * 64 + tile) * 128 + tl;
    const float tx = pos_t[3*t], ty = pos_t[3*t+1], tz = pos_t[3*t+2];

    const int sbeg = half * (NS / 2);
    float d0 = 1e30f, d1 = 1e30f, d2 = 1e30f;
    int   i0 = sbeg,  i1 = sbeg,  i2 = sbeg;

    #pragma unroll 4
    for (int s = sbeg; s < sbeg + NS/2; ++s) {
        float4 p = sp[s];
        float dx = tx - p.x, dy = ty - p.y, dz = tz - p.z;
        float d  = fmaf(dz, dz, fmaf(dy, dy, dx * dx));
        if (d < d2) {
            if (d < d1) {
                d2 = d1; i2 = i1;
                if (d < d0) { d1 = d0; i1 = i0; d0 = d; i0 = s; }
                else        { d1 = d;  i1 = s; }
            } else { d2 = d; i2 = s; }
        }
    }

    // exchange with partner (lane^1) and merge on the even thread
    const unsigned m = 0xffffffffu;
    float e0 = __shfl_xor_sync(m, d0, 1);
    float e1 = __shfl_xor_sync(m, d1, 1);
    float e2 = __shfl_xor_sync(m, d2, 1);
    int   j0 = __shfl_xor_sync(m, i0, 1);
    int   j1 = __shfl_xor_sync(m, i1, 1);
    int   j2 = __shfl_xor_sync(m, i2, 1);

    if (half == 0) {
        // insert partner's sorted triple (strict < keeps lower-index on ties)
        auto ins = [&](float d, int s) {
            if (d < d2) {
                if (d < d1) {
                    d2 = d1; i2 = i1;
                    if (d < d0) { d1 = d0; i1 = i0; d0 = d; i0 = s; }
                    else        { d1 = d;  i1 = s; }
                } else { d2 = d; i2 = s; }
            }
        };
        ins(e0, j0); ins(e1, j1); ins(e2, j2);

        const float w0 = 1.f / fmaxf(d0, 1e-16f);
        const float w1 = 1.f / fmaxf(d1, 1e-16f);
        const float w2 = 1.f / fmaxf(d2, 1e-16f);
        const float inv = 1.f / (w0 + w1 + w2);

        g_knn_w[3*t+0] = w0 * inv;
        g_knn_w[3*t+1] = w1 * inv;
        g_knn_w[3*t+2] = w2 * inv;
        g_knn_idx[3*t+0] = b * NS + i0;
        g_knn_idx[3*t+1] = b * NS + i1;
        g_knn_idx[3*t+2] = b * NS + i2;
    }
}

// ============================================================
// Fused kernel: gather + cvt + GEMM1 + GEMM2, one 128-row tile/CTA.
// 512 threads (16 warps). All A operands smem-resident; weights
// streamed via 3-stage cp.async (L2-resident; reused by all CTAs).
// ============================================================
#define X_LD   136                     // 128 + 8 pad (halves)
#define I_LD   264                     // 256 + 8
#define H_LD   264
#define B1_LD  264
#define B2_LD  136
#define SZ_X   (128 * X_LD)            // 17408
#define SZ_I   (128 * I_LD)            // 33792
#define SZ_H   (128 * H_LD)            // 33792
#define B1_STG (KC * B1_LD)            // 8448
#define B2_STG (KC * B2_LD)            // 4352
#define SZ_S   (3 * B1_STG)            // 25344
#define OFF_X  0
#define OFF_I  (OFF_X + SZ_X)
#define OFF_H  (OFF_I + SZ_I)
#define OFF_S  (OFF_H + SZ_H)
#define FUSED_SMEM ((OFF_S + SZ_S) * 2)   // 220672 bytes

using FragA = wmma::fragment<wmma::matrix_a, 16, 16, 16, __half, wmma::row_major>;
using FragB = wmma::fragment<wmma::matrix_b, 16, 16, 16, __half, wmma::row_major>;
using FragC = wmma::fragment<wmma::accumulator, 16, 16, 16, float>;

__global__ __launch_bounds__(512, 1)
void fused_kernel(const float* __restrict__ xt,
                  const float* __restrict__ xs,
                  const float* __restrict__ b1,
                  float* __restrict__ out)
{
    extern __shared__ __align__(16) __half sh[];
    __half* sX = sh + OFF_X;
    __half* sI = sh + OFF_I;
    __half* sH = sh + OFF_H;
    __half* sS = sh + OFF_S;

    const int m0   = blockIdx.x * 128;
    const int tid  = threadIdx.x;
    const int w    = tid >> 5;
    const int lane = tid & 31;

    // ---- B1 staging lambda (W1 rows [it*32, +32), 256 cols) ----
    auto stageB1 = [&](int it) {
        __half* d = sS + (it % 3) * B1_STG;
        const __half* src = g_W1_h + (size_t)it * KC * C_HID;
        #pragma unroll
        for (int t = 0; t < 2; ++t) {
            const int i  = tid + t * 512;          // 1024 x 16B
            const int r  = i >> 5;
            const int c8 = (i & 31) << 3;
            cp16h(&d[r * B1_LD + c8], src + r * C_HID + c8);
        }
        cp_commit();
    };
    stageB1(0);
    stageB1(1);   // overlap with gather below

    // ---- convert xt tile -> sX (half) ----
    #pragma unroll
    for (int t = 0; t < 8; ++t) {
        const int i  = tid + t * 512;              // 4096 float4
        const int r  = i >> 5;
        const int c4 = (i & 31) << 2;
        float4 v = *(const float4*)(xt + (size_t)(m0 + r) * C_TGT + c4);
        __half2* p = (__half2*)&sX[r * X_LD + c4];
        p[0] = __floats2half2_rn(v.x, v.y);
        p[1] = __floats2half2_rn(v.z, v.w);
    }

    // ---- interp gather -> sI (half); one warp per row ----
    #pragma unroll
    for (int iter = 0; iter < 8; ++iter) {
        const int rr  = iter * 16 + w;
        const int row = m0 + rr;
        const int   i0 = g_knn_idx[3*row+0];
        const int   i1 = g_knn_idx[3*row+1];
        const int   i2 = g_knn_idx[3*row+2];
        const float w0 = g_knn_w[3*row+0];
        const float w1 = g_knn_w[3*row+1];
        const float w2 = g_knn_w[3*row+2];
        const float4* s0 = (const float4*)(xs + (size_t)i0 * C_SRC);
        const float4* s1 = (const float4*)(xs + (size_t)i1 * C_SRC);
        const float4* s2 = (const float4*)(xs + (size_t)i2 * C_SRC);
        #pragma unroll
        for (int h = 0; h < 2; ++h) {
            const int c = lane + h * 32;            // float4 idx, 64/row
            float4 a = s0[c], b = s1[c], d = s2[c];
            float rx = w0*a.x + w1*b.x + w2*d.x;
            float ry = w0*a.y + w1*b.y + w2*d.y;
            float rz = w0*a.z + w1*b.z + w2*d.z;
            float rw = w0*a.w + w1*b.w + w2*d.w;
            __half2* p = (__half2*)&sI[rr * I_LD + c * 4];
            p[0] = __floats2half2_rn(rx, ry);
            p[1] = __floats2half2_rn(rz, rw);
        }
    }

    // ================= phase 1: H = relu([sX|sI] @ W1 + b1) ==============
    const int wm = w & 3;          // 4 x 32-row groups
    const int wn = w >> 2;         // 4 x 64-col groups (N=256)
    FragC fc[2][4];
    #pragma unroll
    for (int i = 0; i < 2; ++i)
        #pragma unroll
        for (int j = 0; j < 4; ++j)
            wmma::fill_fragment(fc[i][j], 0.f);

    const int N1 = C_IN / KC;      // 12
    for (int it = 0; it < N1; ++it) {
        cp_wait<1>();
        __syncthreads();
        if (it + 2 < N1) stageB1(it + 2);
        else cp_commit();          // keep group count in step
        const __half* sB = sS + (it % 3) * B1_STG;
        #pragma unroll
        for (int k16 = 0; k16 < 2; ++k16) {
            const int kc = it * KC + k16 * 16;
            const __half* aptr; int ald;
            if (kc < C_TGT) { aptr = &sX[kc];         ald = X_LD; }
            else            { aptr = &sI[kc - C_TGT]; ald = I_LD; }
            FragA fa[2];
            FragB fb[4];
            #pragma unroll
            for (int i = 0; i < 2; ++i)
                wmma::load_matrix_sync(fa[i], aptr + (wm*32 + i*16) * ald, ald);
            #pragma unroll
            for (int j = 0; j < 4; ++j)
                wmma::load_matrix_sync(fb[j], &sB[k16*16 * B1_LD + wn*64 + j*16], B1_LD);
            #pragma unroll
            for (int i = 0; i < 2; ++i)
                #pragma unroll
                for (int j = 0; j < 4; ++j)
                    wmma::mma_sync(fc[i][j], fa[i], fb[j], fc[i][j]);
        }
    }
    __syncthreads();

    // ---- epilogue 1: bias + relu -> sH (half), via per-warp fp32 scratch ----
    float* scr = (float*)sS + w * 256;     // 16x16 fp32 per warp
    #pragma unroll
    for (int i = 0; i < 2; ++i) {
        #pragma unroll
        for (int j = 0; j < 4; ++j) {
            wmma::store_matrix_sync(scr, fc[i][j], 16, wmma::mem_row_major);
            __syncwarp();
            #pragma unroll
            for (int q = 0; q < 4; ++q) {
                const int e2  = q * 32 + lane;      // 128 half2
                const int rr  = e2 >> 3;
                const int cc2 = e2 & 7;
                const int col = wn*64 + j*16 + cc2*2;
                const int row = wm*32 + i*16 + rr;
                float vx = fmaxf(scr[rr*16 + cc2*2]     + b1[col],   0.f);
                float vy = fmaxf(scr[rr*16 + cc2*2 + 1] + b1[col+1], 0.f);
                *(__half2*)&sH[row * H_LD + col] = __floats2half2_rn(vx, vy);
            }
            __syncwarp();
        }
    }
    __syncthreads();

    // ================= phase 2: out = relu([sH|sX|sI] @ Wcat + bcat) =====
    auto stageB2 = [&](int it) {
        __half* d = sS + (it % 3) * B2_STG;
        const __half* src = g_Wcat_h + (size_t)it * KC * C_OUT;
        const int r  = tid >> 4;                    // 512 x 16B exactly
        const int c8 = (tid & 15) << 3;
        cp16h(&d[r * B2_LD + c8], src + r * C_OUT + c8);
        cp_commit();
    };
    stageB2(0);
    stageB2(1);

    const int wm2 = w & 7;         // 8 x 16-row groups
    const int wn2 = w >> 3;        // 2 x 64-col groups (N=128)
    FragC f2[4];
    #pragma unroll
    for (int j = 0; j < 4; ++j)
        wmma::fill_fragment(f2[j], 0.f);

    const int N2 = (C_HID + C_IN) / KC;   // 20
    for (int it = 0; it < N2; ++it) {
        cp_wait<1>();
        __syncthreads();
        if (it + 2 < N2) stageB2(it + 2);
        else cp_commit();
        const __half* sB = sS + (it % 3) * B2_STG;
        #pragma unroll
        for (int k16 = 0; k16 < 2; ++k16) {
            const int kc = it * KC + k16 * 16;
            const __half* aptr; int ald;
            if      (kc < 256) { aptr = &sH[kc];       ald = H_LD; }
            else if (kc < 384) { aptr = &sX[kc - 256]; ald = X_LD; }
            else               { aptr = &sI[kc - 384]; ald = I_LD; }
            FragA fa;
            FragB fb[4];
            wmma::load_matrix_sync(fa, aptr + (wm2*16) * ald, ald);
            #pragma unroll
            for (int j = 0; j < 4; ++j)
                wmma::load_matrix_sync(fb[j], &sB[k16*16 * B2_LD + wn2*64 + j*16], B2_LD);
            #pragma unroll
            for (int j = 0; j < 4; ++j)
                wmma::mma_sync(f2[j], fa, fb[j], f2[j]);
        }
    }
    __syncthreads();

    // ---- epilogue 2: bcat + relu -> fp32 out ----
    #pragma unroll
    for (int j = 0; j < 4; ++j) {
        wmma::store_matrix_sync(scr, f2[j], 16, wmma::mem_row_major);
        __syncwarp();
        #pragma unroll
        for (int q = 0; q < 2; ++q) {
            const int e4  = q * 32 + lane;          // 64 float4
            const int rr  = e4 >> 2;
            const int cc4 = (e4 & 3) << 2;
            const int col = wn2*64 + j*16 + cc4;
            float4 v = *(float4*)&scr[rr*16 + cc4];
            v.x = fmaxf(v.x + g_bcat[col+0], 0.f);
            v.y = fmaxf(v.y + g_bcat[col+1], 0.f);
            v.z = fmaxf(v.z + g_bcat[col+2], 0.f);
            v.w = fmaxf(v.w + g_bcat[col+3], 0.f);
            *(float4*)&out[(size_t)(m0 + wm2*16 + rr) * C_OUT + col] = v;
        }
        __syncwarp();
    }
}

// ============================================================
// Launch.
// ============================================================
extern "C" void kernel_launch(void* const* d_in, const int* in_sizes, int n_in,
                              void* d_out, int out_size)
{
    const float* xt = (const float*)d_in[0];
    const float* pt = (const float*)d_in[1];
    const float* xs = (const float*)d_in[3];
    const float* ps = (const float*)d_in[4];
    const float* W1 = (const float*)d_in[6];
    const float* b1 = (const float*)d_in[7];
    const float* W2 = (const float*)d_in[8];
    const float* b2 = (const float*)d_in[9];
    const float* Ws = (const float*)d_in[10];
    const float* bs = (const float*)d_in[11];
    float* out = (float*)d_out;

    cudaFuncSetAttribute(fused_kernel, cudaFuncAttributeMaxDynamicSharedMemorySize, FUSED_SMEM);

    cvt_weights_kernel<<<(C_IN * C_HID + 255) / 256, 256>>>(W1, W2, Ws, b2, bs);
    knn_kernel        <<<BATCH * (NT / 128), 256>>>(pt, ps);
    fused_kernel      <<<NTOT / 128, 512, FUSED_SMEM>>>(xt, xs, b1, out);
}